// round 11
// baseline (speedup 1.0000x reference)
#include <cuda_runtime.h>
#include <cuda_bf16.h>
#include <math.h>
#include <stdint.h>

#define D_MODEL 1024
#define T_SEQ   2048
#define B_BATCH 2
#define H_HEADS 16
#define M_ROWS  (B_BATCH * T_SEQ)   // 4096

// ---------------- scratch (__device__ globals; no allocations) ----------------
__device__ __nv_bfloat16 g_xh[(size_t)3 * M_ROWS * D_MODEL];  // input splits (q,k,v)
__device__ __nv_bfloat16 g_xl[(size_t)3 * M_ROWS * D_MODEL];
__device__ __nv_bfloat16 g_wh[(size_t)4 * D_MODEL * D_MODEL]; // weight splits (q,k,v,o)
__device__ __nv_bfloat16 g_wl[(size_t)4 * D_MODEL * D_MODEL];
__device__ __nv_bfloat16 g_qh[(size_t)M_ROWS * D_MODEL];
__device__ __nv_bfloat16 g_ql[(size_t)M_ROWS * D_MODEL];
__device__ __nv_bfloat16 g_kh[(size_t)M_ROWS * D_MODEL];
__device__ __nv_bfloat16 g_kl[(size_t)M_ROWS * D_MODEL];
__device__ __nv_bfloat16 g_vh[(size_t)M_ROWS * D_MODEL];
__device__ __nv_bfloat16 g_vl[(size_t)M_ROWS * D_MODEL];
__device__ __nv_bfloat16 g_ah[(size_t)M_ROWS * D_MODEL];      // attn out split
__device__ __nv_bfloat16 g_al[(size_t)M_ROWS * D_MODEL];

// ---------------- helpers ----------------
__device__ __forceinline__ uint32_t smem_u32(const void* p) {
    uint32_t a;
    asm("{ .reg .u64 t; cvta.to.shared.u64 t, %1; cvt.u32.u64 %0, t; }" : "=r"(a) : "l"(p));
    return a;
}
__device__ __forceinline__ void ldsm_x4(uint32_t (&r)[4], uint32_t addr) {
    asm volatile("ldmatrix.sync.aligned.m8n8.x4.shared.b16 {%0,%1,%2,%3}, [%4];"
        : "=r"(r[0]), "=r"(r[1]), "=r"(r[2]), "=r"(r[3]) : "r"(addr));
}
__device__ __forceinline__ void ldsm_x4t(uint32_t (&r)[4], uint32_t addr) {
    asm volatile("ldmatrix.sync.aligned.m8n8.x4.trans.shared.b16 {%0,%1,%2,%3}, [%4];"
        : "=r"(r[0]), "=r"(r[1]), "=r"(r[2]), "=r"(r[3]) : "r"(addr));
}
__device__ __forceinline__ void ldsm_x2(uint32_t (&r)[2], uint32_t addr) {
    asm volatile("ldmatrix.sync.aligned.m8n8.x2.shared.b16 {%0,%1}, [%2];"
        : "=r"(r[0]), "=r"(r[1]) : "r"(addr));
}
__device__ __forceinline__ void mma16816(float (&d)[4], const uint32_t (&a)[4],
                                         uint32_t b0, uint32_t b1) {
    asm volatile("mma.sync.aligned.m16n8k16.row.col.f32.bf16.bf16.f32 "
        "{%0,%1,%2,%3}, {%4,%5,%6,%7}, {%8,%9}, {%0,%1,%2,%3};"
        : "+f"(d[0]), "+f"(d[1]), "+f"(d[2]), "+f"(d[3])
        : "r"(a[0]), "r"(a[1]), "r"(a[2]), "r"(a[3]), "r"(b0), "r"(b1));
}
__device__ __forceinline__ void cvt_split2(float x, float y, uint32_t& hi, uint32_t& lo) {
    __nv_bfloat16 hx = __float2bfloat16(x), hy = __float2bfloat16(y);
    float rx = x - __bfloat162float(hx), ry = y - __bfloat162float(hy);
    __nv_bfloat162 h2; h2.x = hx; h2.y = hy;
    __nv_bfloat162 l2; l2.x = __float2bfloat16(rx); l2.y = __float2bfloat16(ry);
    hi = *(uint32_t*)&h2; lo = *(uint32_t*)&l2;
}
__device__ __forceinline__ void cp_async16(uint32_t dst, const void* src) {
    asm volatile("cp.async.cg.shared.global [%0], [%1], 16;" :: "r"(dst), "l"(src));
}
#define CP_COMMIT() asm volatile("cp.async.commit_group;" ::: "memory")
#define CP_WAIT(n)  asm volatile("cp.async.wait_group %0;" :: "n"(n) : "memory")
#define CP_WAIT_ALL() asm volatile("cp.async.wait_all;" ::: "memory")

// ---------------- batched fp32 -> bf16 hi/lo split ----------------
struct ConvBatch {
    const float* src[4];
    __nv_bfloat16* hi[4];
    __nv_bfloat16* lo[4];
    int n4;
};
__global__ __launch_bounds__(256) void conv_split_batched(ConvBatch a)
{
    int z = blockIdx.y;
    int i = blockIdx.x * 256 + threadIdx.x;
    if (i >= a.n4) return;
    float4 v = ((const float4*)a.src[z])[i];
    uint32_t h0, l0, h1, l1;
    cvt_split2(v.x, v.y, h0, l0);
    cvt_split2(v.z, v.w, h1, l1);
    ((uint2*)a.hi[z])[i] = make_uint2(h0, h1);
    ((uint2*)a.lo[z])[i] = make_uint2(l0, l1);
}

// ---------------- mma.sync GEMM (batched over z, 3-stage cp.async) ----------------
#define G_STRIDE_B   80
#define G_TILE_B     (128 * G_STRIDE_B)
#define G_STAGE_B    (4 * G_TILE_B)
#define G_SMEM_B     (3 * G_STAGE_B)          // 122880
#define G_NC         (D_MODEL / 32)           // 32

struct GemmUnit {
    const __nv_bfloat16 *Ah, *Al, *Wh, *Wl;
    const float* bias;
    float* C;
    __nv_bfloat16 *Ch, *Cl;
};
struct GemmBatch { GemmUnit g[3]; };

__global__ __launch_bounds__(256) void gemm_mma_kernel(GemmBatch batch, int split_out)
{
    extern __shared__ char smem[];
    const GemmUnit& G = batch.g[blockIdx.z];
    const uint32_t sbase = smem_u32(smem);
    const int tid  = threadIdx.x;
    const int wid  = tid >> 5;
    const int lane = tid & 31;
    const int wm   = wid >> 2;
    const int wn   = wid & 3;
    const int m0 = blockIdx.y * 128;
    const int n0 = blockIdx.x * 128;

    const __nv_bfloat16* base[4] = {
        G.Ah + (size_t)m0 * D_MODEL, G.Al + (size_t)m0 * D_MODEL,
        G.Wh + (size_t)n0 * D_MODEL, G.Wl + (size_t)n0 * D_MODEL
    };

    float acc[4][4][4];
#pragma unroll
    for (int i = 0; i < 4; i++)
#pragma unroll
        for (int j = 0; j < 4; j++)
#pragma unroll
            for (int k = 0; k < 4; k++) acc[i][j][k] = 0.f;

    auto issue_chunk = [&](int c, int s) {
#pragma unroll
        for (int it = 0; it < 8; it++) {
            int g   = tid + it * 256;
            int p   = g >> 9;
            int idx = g & 511;
            int row = idx >> 2;
            int ch  = idx & 3;
            uint32_t dst = sbase + s * G_STAGE_B + p * G_TILE_B + row * G_STRIDE_B + ch * 16;
            cp_async16(dst, base[p] + (size_t)row * D_MODEL + c * 32 + ch * 8);
        }
    };

    const int a_row = wm * 64 + (lane & 7) + ((lane >> 3) & 1) * 8;
    const int a_cho = (lane >> 4) & 1;
    const int b_row = wn * 32 + (lane & 7);
    const int b_cho = (lane >> 3) & 1;

    auto compute = [&](int s) {
        const uint32_t st  = sbase + s * G_STAGE_B;
        const uint32_t aHb = st + a_row * G_STRIDE_B + a_cho * 16;
        const uint32_t bHb = st + 2 * G_TILE_B + b_row * G_STRIDE_B + b_cho * 16;
#pragma unroll
        for (int ks = 0; ks < 2; ks++) {
            uint32_t aks = aHb + ks * 32;
            uint32_t bks = bHb + ks * 32;
            uint32_t aH[4][4], aL[4][4];
#pragma unroll
            for (int mi = 0; mi < 4; mi++) {
                ldsm_x4(aH[mi], aks + mi * (16 * G_STRIDE_B));
                ldsm_x4(aL[mi], aks + G_TILE_B + mi * (16 * G_STRIDE_B));
            }
#pragma unroll
            for (int ni = 0; ni < 4; ni++) {
                uint32_t bH[2], bL[2];
                ldsm_x2(bH, bks + ni * (8 * G_STRIDE_B));
                ldsm_x2(bL, bks + G_TILE_B + ni * (8 * G_STRIDE_B));
#pragma unroll
                for (int mi = 0; mi < 4; mi++) {
                    mma16816(acc[mi][ni], aH[mi], bH[0], bH[1]);
                    mma16816(acc[mi][ni], aH[mi], bL[0], bL[1]);
                    mma16816(acc[mi][ni], aL[mi], bH[0], bH[1]);
                }
            }
        }
    };

    // 3-stage async pipeline
    issue_chunk(0, 0); CP_COMMIT();
    issue_chunk(1, 1); CP_COMMIT();
    issue_chunk(2, 2); CP_COMMIT();
    CP_WAIT(2);
    __syncthreads();
    for (int c = 0; c < G_NC; c++) {
        compute(c % 3);
        __syncthreads();
        if (c + 3 < G_NC) issue_chunk(c + 3, c % 3);
        CP_COMMIT();
        CP_WAIT(2);
        __syncthreads();
    }

    const int mb = m0 + wm * 64;
    const int nb = n0 + wn * 32;
    const int rl = lane >> 2;
    const int cl = 2 * (lane & 3);
#pragma unroll
    for (int ni = 0; ni < 4; ni++) {
        int cc = nb + ni * 8 + cl;
        float2 bv = *(const float2*)(G.bias + cc);
#pragma unroll
        for (int mi = 0; mi < 4; mi++) {
            int r0 = mb + mi * 16 + rl;
            float x0 = acc[mi][ni][0] + bv.x, y0 = acc[mi][ni][1] + bv.y;
            float x1 = acc[mi][ni][2] + bv.x, y1 = acc[mi][ni][3] + bv.y;
            if (split_out) {
                uint32_t h0, l0, h1, l1;
                cvt_split2(x0, y0, h0, l0);
                cvt_split2(x1, y1, h1, l1);
                *(uint32_t*)(G.Ch + (size_t)r0 * D_MODEL + cc)       = h0;
                *(uint32_t*)(G.Cl + (size_t)r0 * D_MODEL + cc)       = l0;
                *(uint32_t*)(G.Ch + (size_t)(r0 + 8) * D_MODEL + cc) = h1;
                *(uint32_t*)(G.Cl + (size_t)(r0 + 8) * D_MODEL + cc) = l1;
            } else {
                *(float2*)(G.C + (size_t)r0 * D_MODEL + cc)       = make_float2(x0, y0);
                *(float2*)(G.C + (size_t)(r0 + 8) * D_MODEL + cc) = make_float2(x1, y1);
            }
        }
    }
}

// ---------------------------------------------------------------------------
// mma.sync flash attention: 64 q rows x (b,h) per CTA, 128 threads (4 warps),
// 2 CTAs/SM for cross-CTA softmax/MMA overlap. 2-stage cp.async K/V ring.
// Order per tile: QK -> softmax -> PV (R8 order).
// ---------------------------------------------------------------------------
#define A_STRIDE  144
#define A_QSZ     (64 * A_STRIDE)             // 9216 per Q part
#define A_KSZ     (64 * A_STRIDE)             // 9216 per K/V part
#define A_STAGE   (4 * A_KSZ + 256)           // Kh,Kl,Vh,Vl + mask(int)
#define A_SMEM    (2 * A_QSZ + 2 * A_STAGE)   // 92672
#define A_NITER   (T_SEQ / 64)

__global__ __launch_bounds__(128, 2) void attn_mma_kernel(const int* __restrict__ mask)
{
    extern __shared__ char smem[];
    const uint32_t sbase = smem_u32(smem);
    const int tid  = threadIdx.x;
    const int w    = tid >> 5;                // 0..3
    const int lane = tid & 31;
    const int qt   = blockIdx.x;              // 0..31 (64 q rows each)
    const int bh   = blockIdx.y;
    const int b    = bh >> 4;
    const int h    = bh & 15;

    const size_t qoff = (size_t)(b * T_SEQ + qt * 64) * D_MODEL + h * 64;
    const size_t koff = (size_t)(b * T_SEQ) * D_MODEL + h * 64;
    const int* mb = mask + b * T_SEQ;

    auto issue_stage = [&](int it, int s) {
        const size_t soff = koff + (size_t)(it * 64) * D_MODEL;
        const __nv_bfloat16* srcs[4] = { g_kh + soff, g_kl + soff, g_vh + soff, g_vl + soff };
        const uint32_t sb = sbase + 2 * A_QSZ + s * A_STAGE;
#pragma unroll
        for (int i2 = 0; i2 < 16; i2++) {
            int g = tid + i2 * 128;           // 0..2047
            int p = g >> 9;                   // Kh,Kl,Vh,Vl
            int idx = g & 511;
            int row = idx >> 3, ch = idx & 7;
            cp_async16(sb + p * A_KSZ + row * A_STRIDE + ch * 16,
                       srcs[p] + (size_t)row * D_MODEL + ch * 8);
        }
        if (tid < 16)
            cp_async16(sb + 4 * A_KSZ + tid * 16, mb + it * 64 + tid * 4);
    };

    // prefetch stage 0 while we stage Q
    issue_stage(0, 0); CP_COMMIT();

    // ---- stage pre-split Q tile (64 rows) into smem ----
    {
        const __nv_bfloat16* srcs[2] = { g_qh + qoff, g_ql + qoff };
#pragma unroll
        for (int i = 0; i < 8; i++) {
            int g = tid + i * 128;            // 0..1023 uint4 slots
            int p = g >> 9;                   // 0=hi 1=lo
            int idx = g & 511;
            int row = idx >> 3, ch = idx & 7;
            uint4 v = *(const uint4*)(srcs[p] + (size_t)row * D_MODEL + ch * 8);
            *(uint4*)(smem + p * A_QSZ + row * A_STRIDE + ch * 16) = v;
        }
    }
    __syncthreads();

    // ---- per-warp Q fragments (rows 16w..16w+15) ----
    uint32_t Qh[4][4], Ql[4][4];
    {
        const int a_row = 16 * w + (lane & 7) + 8 * ((lane >> 3) & 1);
        const uint32_t abase = sbase + a_row * A_STRIDE + ((lane >> 4) & 1) * 16;
#pragma unroll
        for (int kf = 0; kf < 4; kf++) {
            ldsm_x4(Qh[kf], abase + kf * 32);
            ldsm_x4(Ql[kf], abase + A_QSZ + kf * 32);
        }
    }

    float O[8][4];
#pragma unroll
    for (int i = 0; i < 8; i++)
#pragma unroll
        for (int j = 0; j < 4; j++) O[i][j] = 0.f;
    float m0r = -1e30f, m1r = -1e30f, l0r = 0.f, l1r = 0.f;

    const float SCALE = 0.125f;

    for (int it = 0; it < A_NITER; it++) {
        // prefetch next stage into the other buffer (safe: last reader of that
        // buffer finished before the __syncthreads at the end of iter it-1)
        if (it + 1 < A_NITER) { issue_stage(it + 1, (it + 1) & 1); CP_COMMIT(); }

        // stage `it` ready (1 outstanding group = the one just issued)
        if (it + 1 < A_NITER) CP_WAIT(1); else CP_WAIT_ALL();
        __syncthreads();

        const uint32_t stb = sbase + 2 * A_QSZ + (it & 1) * A_STAGE;
        const uint32_t kb  = stb;
        const uint32_t vb  = stb + 2 * A_KSZ;
        const uint32_t mbx = stb + 4 * A_KSZ;

        // ---- S = Q K^T (3-term split) ----
        float S[8][4];
#pragma unroll
        for (int i = 0; i < 8; i++)
#pragma unroll
            for (int j = 0; j < 4; j++) S[i][j] = 0.f;
        {
            const uint32_t kaddr0 = kb + (lane & 7) * A_STRIDE + (lane >> 3) * 16;
#pragma unroll
            for (int kp = 0; kp < 2; kp++) {
#pragma unroll
                for (int nf = 0; nf < 8; nf++) {
                    uint32_t bh4[4], bl4[4];
                    uint32_t addr = kaddr0 + nf * (8 * A_STRIDE) + kp * 64;
                    ldsm_x4(bh4, addr);
                    ldsm_x4(bl4, addr + A_KSZ);
                    mma16816(S[nf], Qh[2 * kp],     bh4[0], bh4[1]);
                    mma16816(S[nf], Qh[2 * kp],     bl4[0], bl4[1]);
                    mma16816(S[nf], Ql[2 * kp],     bh4[0], bh4[1]);
                    mma16816(S[nf], Qh[2 * kp + 1], bh4[2], bh4[3]);
                    mma16816(S[nf], Qh[2 * kp + 1], bl4[2], bl4[3]);
                    mma16816(S[nf], Ql[2 * kp + 1], bh4[2], bh4[3]);
                }
            }
        }

        // ---- softmax ----
        uint32_t Ph[4][4], Pl[4][4];
        {
            float mx0 = -1e30f, mx1 = -1e30f;
            float mkx[8], mky[8];
#pragma unroll
            for (int f = 0; f < 8; f++) {
                int2 mk = *(int2*)(smem + (mbx - sbase) + (8 * f + 2 * (lane & 3)) * 4);
                mkx[f] = (mk.x != 0) ? 1.0f : 0.0f;
                mky[f] = (mk.y != 0) ? 1.0f : 0.0f;
                S[f][0] = (mk.x != 0) ? S[f][0] * SCALE : -1e30f;
                S[f][1] = (mk.y != 0) ? S[f][1] * SCALE : -1e30f;
                S[f][2] = (mk.x != 0) ? S[f][2] * SCALE : -1e30f;
                S[f][3] = (mk.y != 0) ? S[f][3] * SCALE : -1e30f;
                mx0 = fmaxf(mx0, fmaxf(S[f][0], S[f][1]));
                mx1 = fmaxf(mx1, fmaxf(S[f][2], S[f][3]));
            }
            mx0 = fmaxf(mx0, __shfl_xor_sync(0xffffffffu, mx0, 1));
            mx0 = fmaxf(mx0, __shfl_xor_sync(0xffffffffu, mx0, 2));
            mx1 = fmaxf(mx1, __shfl_xor_sync(0xffffffffu, mx1, 1));
            mx1 = fmaxf(mx1, __shfl_xor_sync(0xffffffffu, mx1, 2));

            float mn0 = fmaxf(m0r, mx0), mn1 = fmaxf(m1r, mx1);
            float c0 = __expf(m0r - mn0), c1 = __expf(m1r - mn1);

            float rs0 = 0.f, rs1 = 0.f;
#pragma unroll
            for (int f = 0; f < 8; f++) {
                float p0 = __expf(S[f][0] - mn0) * mkx[f];
                float p1 = __expf(S[f][1] - mn0) * mky[f];
                float p2 = __expf(S[f][2] - mn1) * mkx[f];
                float p3 = __expf(S[f][3] - mn1) * mky[f];
                rs0 += p0 + p1;
                rs1 += p2 + p3;
                uint32_t h01, l01, h23, l23;
                cvt_split2(p0, p1, h01, l01);
                cvt_split2(p2, p3, h23, l23);
                int kf = f >> 1, half = (f & 1) * 2;
                Ph[kf][half]     = h01;  Ph[kf][half + 1] = h23;
                Pl[kf][half]     = l01;  Pl[kf][half + 1] = l23;
            }
            rs0 += __shfl_xor_sync(0xffffffffu, rs0, 1);
            rs0 += __shfl_xor_sync(0xffffffffu, rs0, 2);
            rs1 += __shfl_xor_sync(0xffffffffu, rs1, 1);
            rs1 += __shfl_xor_sync(0xffffffffu, rs1, 2);

            l0r = l0r * c0 + rs0;  m0r = mn0;
            l1r = l1r * c1 + rs1;  m1r = mn1;
#pragma unroll
            for (int i = 0; i < 8; i++) {
                O[i][0] *= c0; O[i][1] *= c0;
                O[i][2] *= c1; O[i][3] *= c1;
            }
        }

        // ---- O += P V ----
        {
            const uint32_t vaddr0 = vb + ((lane & 7) + 8 * ((lane >> 3) & 1)) * A_STRIDE
                                       + (lane >> 4) * 16;
#pragma unroll
            for (int np = 0; np < 4; np++) {
#pragma unroll
                for (int kf = 0; kf < 4; kf++) {
                    uint32_t bh4[4], bl4[4];
                    uint32_t addr = vaddr0 + kf * (16 * A_STRIDE) + np * 32;
                    ldsm_x4t(bh4, addr);
                    ldsm_x4t(bl4, addr + A_KSZ);
                    mma16816(O[2 * np],     Ph[kf], bh4[0], bh4[1]);
                    mma16816(O[2 * np],     Ph[kf], bl4[0], bl4[1]);
                    mma16816(O[2 * np],     Pl[kf], bh4[0], bh4[1]);
                    mma16816(O[2 * np + 1], Ph[kf], bh4[2], bh4[3]);
                    mma16816(O[2 * np + 1], Ph[kf], bl4[2], bl4[3]);
                    mma16816(O[2 * np + 1], Pl[kf], bh4[2], bh4[3]);
                }
            }
        }

        __syncthreads();   // all warps done reading stage it&1
    }

    // ---- epilogue: normalize, split, write g_ah/g_al ----
    const float inv0 = (l0r > 0.f) ? (1.0f / l0r) : 0.f;
    const float inv1 = (l1r > 0.f) ? (1.0f / l1r) : 0.f;
    const int grow0 = b * T_SEQ + qt * 64 + 16 * w + (lane >> 2);
    const int colb  = h * 64 + 2 * (lane & 3);
#pragma unroll
    for (int nf = 0; nf < 8; nf++) {
        int col = colb + nf * 8;
        uint32_t h01, l01, h23, l23;
        cvt_split2(O[nf][0] * inv0, O[nf][1] * inv0, h01, l01);
        cvt_split2(O[nf][2] * inv1, O[nf][3] * inv1, h23, l23);
        *(uint32_t*)(g_ah + (size_t)grow0 * D_MODEL + col)       = h01;
        *(uint32_t*)(g_al + (size_t)grow0 * D_MODEL + col)       = l01;
        *(uint32_t*)(g_ah + (size_t)(grow0 + 8) * D_MODEL + col) = h23;
        *(uint32_t*)(g_al + (size_t)(grow0 + 8) * D_MODEL + col) = l23;
    }
}

// ---------------------------------------------------------------------------
extern "C" void kernel_launch(void* const* d_in, const int* in_sizes, int n_in,
                              void* d_out, int out_size)
{
    const float* query = (const float*)d_in[0];
    const float* key   = (const float*)d_in[1];
    const float* value = (const float*)d_in[2];
    const int*   mask  = (const int*)d_in[3];
    const float* Wq = (const float*)d_in[4];
    const float* bq = (const float*)d_in[5];
    const float* Wk = (const float*)d_in[6];
    const float* bk = (const float*)d_in[7];
    const float* Wv = (const float*)d_in[8];
    const float* bv = (const float*)d_in[9];
    const float* Wo = (const float*)d_in[10];
    const float* bo = (const float*)d_in[11];
    float* out = (float*)d_out;

    __nv_bfloat16 *xh, *xl, *wh, *wl, *qh, *ql, *kh, *kl, *vh, *vl, *ah, *al;
    cudaGetSymbolAddress((void**)&xh, g_xh);
    cudaGetSymbolAddress((void**)&xl, g_xl);
    cudaGetSymbolAddress((void**)&wh, g_wh);
    cudaGetSymbolAddress((void**)&wl, g_wl);
    cudaGetSymbolAddress((void**)&qh, g_qh);
    cudaGetSymbolAddress((void**)&ql, g_ql);
    cudaGetSymbolAddress((void**)&kh, g_kh);
    cudaGetSymbolAddress((void**)&kl, g_kl);
    cudaGetSymbolAddress((void**)&vh, g_vh);
    cudaGetSymbolAddress((void**)&vl, g_vl);
    cudaGetSymbolAddress((void**)&ah, g_ah);
    cudaGetSymbolAddress((void**)&al, g_al);

    cudaFuncSetAttribute(gemm_mma_kernel, cudaFuncAttributeMaxDynamicSharedMemorySize, G_SMEM_B);
    cudaFuncSetAttribute(attn_mma_kernel, cudaFuncAttributeMaxDynamicSharedMemorySize, A_SMEM);

    const size_t MD = (size_t)M_ROWS * D_MODEL;
    const size_t DD = (size_t)D_MODEL * D_MODEL;
    const int nact4 = (int)(MD / 4);
    const int nw4   = (int)(DD / 4);

    // split inputs (q,k,v) — one launch
    ConvBatch ca;
    ca.src[0] = query; ca.src[1] = key; ca.src[2] = value; ca.src[3] = query;
    ca.hi[0] = xh;        ca.lo[0] = xl;
    ca.hi[1] = xh + MD;   ca.lo[1] = xl + MD;
    ca.hi[2] = xh + 2*MD; ca.lo[2] = xl + 2*MD;
    ca.hi[3] = xh;        ca.lo[3] = xl;
    ca.n4 = nact4;
    conv_split_batched<<<dim3(nact4 / 256, 3), 256>>>(ca);

    // split weights (q,k,v,o) — one launch
    ConvBatch cw;
    cw.src[0] = Wq; cw.src[1] = Wk; cw.src[2] = Wv; cw.src[3] = Wo;
    for (int i = 0; i < 4; i++) { cw.hi[i] = wh + i * DD; cw.lo[i] = wl + i * DD; }
    cw.n4 = nw4;
    conv_split_batched<<<dim3(nw4 / 256, 4), 256>>>(cw);

    // fused Q/K/V projection (split bf16 outputs)
    GemmBatch gb;
    gb.g[0] = { xh,        xl,        wh,        wl,        bq, nullptr, qh, ql };
    gb.g[1] = { xh + MD,   xl + MD,   wh + DD,   wl + DD,   bk, nullptr, kh, kl };
    gb.g[2] = { xh + 2*MD, xl + 2*MD, wh + 2*DD, wl + 2*DD, bv, nullptr, vh, vl };
    gemm_mma_kernel<<<dim3(D_MODEL / 128, M_ROWS / 128, 3), 256, G_SMEM_B>>>(gb, 1);

    // attention: 64 q rows per CTA, 2 CTAs/SM
    dim3 agrid(T_SEQ / 64, B_BATCH * H_HEADS);   // (32, 32)
    attn_mma_kernel<<<agrid, 128, A_SMEM>>>(mask);

    // output projection (fp32 out)
    GemmBatch go;
    go.g[0] = { ah, al, wh + 3*DD, wl + 3*DD, bo, out, nullptr, nullptr };
    go.g[1] = go.g[0];
    go.g[2] = go.g[0];
    gemm_mma_kernel<<<dim3(D_MODEL / 128, M_ROWS / 128, 1), 256, G_SMEM_B>>>(go, 0);
}

// round 14
// speedup vs baseline: 1.5902x; 1.5902x over previous
#include <cuda_runtime.h>
#include <cuda_bf16.h>
#include <math.h>
#include <stdint.h>

#define D_MODEL 1024
#define T_SEQ   2048
#define B_BATCH 2
#define H_HEADS 16
#define M_ROWS  (B_BATCH * T_SEQ)   // 4096

// ---------------- scratch (__device__ globals; no allocations) ----------------
__device__ __nv_bfloat16 g_xh[(size_t)3 * M_ROWS * D_MODEL];  // input splits (q,k,v)
__device__ __nv_bfloat16 g_xl[(size_t)3 * M_ROWS * D_MODEL];
__device__ __nv_bfloat16 g_wh[(size_t)4 * D_MODEL * D_MODEL]; // weight splits (q,k,v,o)
__device__ __nv_bfloat16 g_wl[(size_t)4 * D_MODEL * D_MODEL];
__device__ __nv_bfloat16 g_qh[(size_t)M_ROWS * D_MODEL];
__device__ __nv_bfloat16 g_ql[(size_t)M_ROWS * D_MODEL];
__device__ __nv_bfloat16 g_kh[(size_t)M_ROWS * D_MODEL];
__device__ __nv_bfloat16 g_kl[(size_t)M_ROWS * D_MODEL];
__device__ __nv_bfloat16 g_vh[(size_t)M_ROWS * D_MODEL];
__device__ __nv_bfloat16 g_vl[(size_t)M_ROWS * D_MODEL];
__device__ __nv_bfloat16 g_ah[(size_t)M_ROWS * D_MODEL];      // attn out split
__device__ __nv_bfloat16 g_al[(size_t)M_ROWS * D_MODEL];

// ---------------- helpers ----------------
__device__ __forceinline__ uint32_t smem_u32(const void* p) {
    uint32_t a;
    asm("{ .reg .u64 t; cvta.to.shared.u64 t, %1; cvt.u32.u64 %0, t; }" : "=r"(a) : "l"(p));
    return a;
}
__device__ __forceinline__ void ldsm_x4(uint32_t (&r)[4], uint32_t addr) {
    asm volatile("ldmatrix.sync.aligned.m8n8.x4.shared.b16 {%0,%1,%2,%3}, [%4];"
        : "=r"(r[0]), "=r"(r[1]), "=r"(r[2]), "=r"(r[3]) : "r"(addr));
}
__device__ __forceinline__ void ldsm_x4t(uint32_t (&r)[4], uint32_t addr) {
    asm volatile("ldmatrix.sync.aligned.m8n8.x4.trans.shared.b16 {%0,%1,%2,%3}, [%4];"
        : "=r"(r[0]), "=r"(r[1]), "=r"(r[2]), "=r"(r[3]) : "r"(addr));
}
__device__ __forceinline__ void ldsm_x2(uint32_t (&r)[2], uint32_t addr) {
    asm volatile("ldmatrix.sync.aligned.m8n8.x2.shared.b16 {%0,%1}, [%2];"
        : "=r"(r[0]), "=r"(r[1]) : "r"(addr));
}
__device__ __forceinline__ void mma16816(float (&d)[4], const uint32_t (&a)[4],
                                         uint32_t b0, uint32_t b1) {
    asm volatile("mma.sync.aligned.m16n8k16.row.col.f32.bf16.bf16.f32 "
        "{%0,%1,%2,%3}, {%4,%5,%6,%7}, {%8,%9}, {%0,%1,%2,%3};"
        : "+f"(d[0]), "+f"(d[1]), "+f"(d[2]), "+f"(d[3])
        : "r"(a[0]), "r"(a[1]), "r"(a[2]), "r"(a[3]), "r"(b0), "r"(b1));
}
__device__ __forceinline__ void cvt_split2(float x, float y, uint32_t& hi, uint32_t& lo) {
    __nv_bfloat16 hx = __float2bfloat16(x), hy = __float2bfloat16(y);
    float rx = x - __bfloat162float(hx), ry = y - __bfloat162float(hy);
    __nv_bfloat162 h2; h2.x = hx; h2.y = hy;
    __nv_bfloat162 l2; l2.x = __float2bfloat16(rx); l2.y = __float2bfloat16(ry);
    hi = *(uint32_t*)&h2; lo = *(uint32_t*)&l2;
}
__device__ __forceinline__ void cp_async16(uint32_t dst, const void* src) {
    asm volatile("cp.async.cg.shared.global [%0], [%1], 16;" :: "r"(dst), "l"(src));
}
#define CP_COMMIT() asm volatile("cp.async.commit_group;" ::: "memory")
#define CP_WAIT(n)  asm volatile("cp.async.wait_group %0;" :: "n"(n) : "memory")

// ---------------- batched fp32 -> bf16 hi/lo split ----------------
struct ConvBatch {
    const float* src[4];
    __nv_bfloat16* hi[4];
    __nv_bfloat16* lo[4];
    int n4;
};
__global__ __launch_bounds__(256) void conv_split_batched(ConvBatch a)
{
    int z = blockIdx.y;
    int i = blockIdx.x * 256 + threadIdx.x;
    if (i >= a.n4) return;
    float4 v = ((const float4*)a.src[z])[i];
    uint32_t h0, l0, h1, l1;
    cvt_split2(v.x, v.y, h0, l0);
    cvt_split2(v.z, v.w, h1, l1);
    ((uint2*)a.hi[z])[i] = make_uint2(h0, h1);
    ((uint2*)a.lo[z])[i] = make_uint2(l0, l1);
}

// ---------------- mma.sync GEMM (batched over z, 3-stage cp.async) ----------------
#define G_STRIDE_B   80
#define G_TILE_B     (128 * G_STRIDE_B)
#define G_STAGE_B    (4 * G_TILE_B)
#define G_SMEM_B     (3 * G_STAGE_B)          // 122880
#define G_NC         (D_MODEL / 32)           // 32

struct GemmUnit {
    const __nv_bfloat16 *Ah, *Al, *Wh, *Wl;
    const float* bias;
    float* C;
    __nv_bfloat16 *Ch, *Cl;
};
struct GemmBatch { GemmUnit g[3]; };

__global__ __launch_bounds__(256) void gemm_mma_kernel(GemmBatch batch, int split_out)
{
    extern __shared__ char smem[];
    const GemmUnit& G = batch.g[blockIdx.z];
    const uint32_t sbase = smem_u32(smem);
    const int tid  = threadIdx.x;
    const int wid  = tid >> 5;
    const int lane = tid & 31;
    const int wm   = wid >> 2;
    const int wn   = wid & 3;
    const int m0 = blockIdx.y * 128;
    const int n0 = blockIdx.x * 128;

    const __nv_bfloat16* base[4] = {
        G.Ah + (size_t)m0 * D_MODEL, G.Al + (size_t)m0 * D_MODEL,
        G.Wh + (size_t)n0 * D_MODEL, G.Wl + (size_t)n0 * D_MODEL
    };

    float acc[4][4][4];
#pragma unroll
    for (int i = 0; i < 4; i++)
#pragma unroll
        for (int j = 0; j < 4; j++)
#pragma unroll
            for (int k = 0; k < 4; k++) acc[i][j][k] = 0.f;

    auto issue_chunk = [&](int c, int s) {
#pragma unroll
        for (int it = 0; it < 8; it++) {
            int g   = tid + it * 256;
            int p   = g >> 9;
            int idx = g & 511;
            int row = idx >> 2;
            int ch  = idx & 3;
            uint32_t dst = sbase + s * G_STAGE_B + p * G_TILE_B + row * G_STRIDE_B + ch * 16;
            cp_async16(dst, base[p] + (size_t)row * D_MODEL + c * 32 + ch * 8);
        }
    };

    const int a_row = wm * 64 + (lane & 7) + ((lane >> 3) & 1) * 8;
    const int a_cho = (lane >> 4) & 1;
    const int b_row = wn * 32 + (lane & 7);
    const int b_cho = (lane >> 3) & 1;

    auto compute = [&](int s) {
        const uint32_t st  = sbase + s * G_STAGE_B;
        const uint32_t aHb = st + a_row * G_STRIDE_B + a_cho * 16;
        const uint32_t bHb = st + 2 * G_TILE_B + b_row * G_STRIDE_B + b_cho * 16;
#pragma unroll
        for (int ks = 0; ks < 2; ks++) {
            uint32_t aks = aHb + ks * 32;
            uint32_t bks = bHb + ks * 32;
            uint32_t aH[4][4], aL[4][4];
#pragma unroll
            for (int mi = 0; mi < 4; mi++) {
                ldsm_x4(aH[mi], aks + mi * (16 * G_STRIDE_B));
                ldsm_x4(aL[mi], aks + G_TILE_B + mi * (16 * G_STRIDE_B));
            }
#pragma unroll
            for (int ni = 0; ni < 4; ni++) {
                uint32_t bH[2], bL[2];
                ldsm_x2(bH, bks + ni * (8 * G_STRIDE_B));
                ldsm_x2(bL, bks + G_TILE_B + ni * (8 * G_STRIDE_B));
#pragma unroll
                for (int mi = 0; mi < 4; mi++) {
                    mma16816(acc[mi][ni], aH[mi], bH[0], bH[1]);
                    mma16816(acc[mi][ni], aH[mi], bL[0], bL[1]);
                    mma16816(acc[mi][ni], aL[mi], bH[0], bH[1]);
                }
            }
        }
    };

    // 3-stage async pipeline
    issue_chunk(0, 0); CP_COMMIT();
    issue_chunk(1, 1); CP_COMMIT();
    issue_chunk(2, 2); CP_COMMIT();
    CP_WAIT(2);
    __syncthreads();
    for (int c = 0; c < G_NC; c++) {
        compute(c % 3);
        __syncthreads();
        if (c + 3 < G_NC) issue_chunk(c + 3, c % 3);
        CP_COMMIT();
        CP_WAIT(2);
        __syncthreads();
    }

    const int mb = m0 + wm * 64;
    const int nb = n0 + wn * 32;
    const int rl = lane >> 2;
    const int cl = 2 * (lane & 3);
#pragma unroll
    for (int ni = 0; ni < 4; ni++) {
        int cc = nb + ni * 8 + cl;
        float2 bv = *(const float2*)(G.bias + cc);
#pragma unroll
        for (int mi = 0; mi < 4; mi++) {
            int r0 = mb + mi * 16 + rl;
            float x0 = acc[mi][ni][0] + bv.x, y0 = acc[mi][ni][1] + bv.y;
            float x1 = acc[mi][ni][2] + bv.x, y1 = acc[mi][ni][3] + bv.y;
            if (split_out) {
                uint32_t h0, l0, h1, l1;
                cvt_split2(x0, y0, h0, l0);
                cvt_split2(x1, y1, h1, l1);
                *(uint32_t*)(G.Ch + (size_t)r0 * D_MODEL + cc)       = h0;
                *(uint32_t*)(G.Cl + (size_t)r0 * D_MODEL + cc)       = l0;
                *(uint32_t*)(G.Ch + (size_t)(r0 + 8) * D_MODEL + cc) = h1;
                *(uint32_t*)(G.Cl + (size_t)(r0 + 8) * D_MODEL + cc) = l1;
            } else {
                *(float2*)(G.C + (size_t)r0 * D_MODEL + cc)       = make_float2(x0, y0);
                *(float2*)(G.C + (size_t)(r0 + 8) * D_MODEL + cc) = make_float2(x1, y1);
            }
        }
    }
}

// ---------------------------------------------------------------------------
// mma.sync flash attention on pre-split bf16 Q/K/V. 128 q rows x (b,h) per block.
// (R8 configuration — measured 336 us.)
// ---------------------------------------------------------------------------
#define A_STRIDE  144
#define A_QSZ     (128 * A_STRIDE)
#define A_KSZ     (64 * A_STRIDE)
#define A_STAGE   (4 * A_KSZ + 512)
#define A_SMEM    (2 * A_QSZ + 2 * A_STAGE)
#define A_NITER   (T_SEQ / 64)

__global__ __launch_bounds__(256, 1) void attn_mma_kernel(const int* __restrict__ mask)
{
    extern __shared__ char smem[];
    const uint32_t sbase = smem_u32(smem);
    const int tid  = threadIdx.x;
    const int w    = tid >> 5;
    const int lane = tid & 31;
    const int qt   = blockIdx.x;
    const int bh   = blockIdx.y;
    const int b    = bh >> 4;
    const int h    = bh & 15;

    const size_t qoff = (size_t)(b * T_SEQ + qt * 128) * D_MODEL + h * 64;
    const size_t koff = (size_t)(b * T_SEQ) * D_MODEL + h * 64;
    const int* mb = mask + b * T_SEQ;

    // ---- load pre-split Q tile (128 rows x 64 bf16, hi+lo) ----
    {
        const __nv_bfloat16* srcs[2] = { g_qh + qoff, g_ql + qoff };
#pragma unroll
        for (int i = 0; i < 8; i++) {
            int g = tid + i * 256;          // 0..2047 uint4 slots
            int p = g >> 10;                // 0=hi 1=lo
            int idx = g & 1023;
            int row = idx >> 3, ch = idx & 7;
            uint4 v = *(const uint4*)(srcs[p] + (size_t)row * D_MODEL + ch * 8);
            *(uint4*)(smem + p * A_QSZ + row * A_STRIDE + ch * 16) = v;
        }
    }
    __syncthreads();

    // ---- per-warp Q fragments ----
    uint32_t Qh[4][4], Ql[4][4];
    {
        const int a_row = 16 * w + (lane & 7) + 8 * ((lane >> 3) & 1);
        const uint32_t abase = sbase + a_row * A_STRIDE + ((lane >> 4) & 1) * 16;
#pragma unroll
        for (int kf = 0; kf < 4; kf++) {
            ldsm_x4(Qh[kf], abase + kf * 32);
            ldsm_x4(Ql[kf], abase + A_QSZ + kf * 32);
        }
    }

    float O[8][4];
#pragma unroll
    for (int i = 0; i < 8; i++)
#pragma unroll
        for (int j = 0; j < 4; j++) O[i][j] = 0.f;
    float m0r = -1e30f, m1r = -1e30f, l0r = 0.f, l1r = 0.f;

    // ---- K/V stage loaders (pure copies, register-staged) ----
    uint4 ldreg[8];
    float mreg = 0.f;
    auto ldg_stage = [&](int it) {
        const size_t soff = koff + (size_t)(it * 64) * D_MODEL;
        const __nv_bfloat16* srcs[4] = { g_kh + soff, g_kl + soff, g_vh + soff, g_vl + soff };
#pragma unroll
        for (int i = 0; i < 8; i++) {
            int g = tid + i * 256;          // 0..2047
            int p = g >> 9;                 // Kh,Kl,Vh,Vl
            int idx = g & 511;
            int row = idx >> 3, ch = idx & 7;
            ldreg[i] = *(const uint4*)(srcs[p] + (size_t)row * D_MODEL + ch * 8);
        }
        if (tid < 64) mreg = (mb[it * 64 + tid] != 0) ? 1.0f : 0.0f;
    };
    auto sts_stage = [&](int s) {
        char* bs = smem + 2 * A_QSZ + s * A_STAGE;
#pragma unroll
        for (int i = 0; i < 8; i++) {
            int g = tid + i * 256;
            int p = g >> 9;
            int idx = g & 511;
            int row = idx >> 3, ch = idx & 7;
            *(uint4*)(bs + p * A_KSZ + row * A_STRIDE + ch * 16) = ldreg[i];
        }
        if (tid < 64) *(float*)(bs + 4 * A_KSZ + tid * 4) = mreg;
    };

    ldg_stage(0);
    sts_stage(0);
    __syncthreads();

    const float SCALE = 0.125f;

    for (int it = 0; it < A_NITER; it++) {
        if (it + 1 < A_NITER) ldg_stage(it + 1);

        const uint32_t stb = sbase + 2 * A_QSZ + (it & 1) * A_STAGE;
        const uint32_t kb  = stb;
        const uint32_t vb  = stb + 2 * A_KSZ;
        const uint32_t mbx = stb + 4 * A_KSZ;

        // ---- S = Q K^T (3-term split) ----
        float S[8][4];
#pragma unroll
        for (int i = 0; i < 8; i++)
#pragma unroll
            for (int j = 0; j < 4; j++) S[i][j] = 0.f;

        {
            const uint32_t kaddr0 = kb + (lane & 7) * A_STRIDE + (lane >> 3) * 16;
#pragma unroll
            for (int kp = 0; kp < 2; kp++) {
#pragma unroll
                for (int nf = 0; nf < 8; nf++) {
                    uint32_t bh4[4], bl4[4];
                    uint32_t addr = kaddr0 + nf * (8 * A_STRIDE) + kp * 64;
                    ldsm_x4(bh4, addr);
                    ldsm_x4(bl4, addr + A_KSZ);
                    mma16816(S[nf], Qh[2 * kp],     bh4[0], bh4[1]);
                    mma16816(S[nf], Qh[2 * kp],     bl4[0], bl4[1]);
                    mma16816(S[nf], Ql[2 * kp],     bh4[0], bh4[1]);
                    mma16816(S[nf], Qh[2 * kp + 1], bh4[2], bh4[3]);
                    mma16816(S[nf], Qh[2 * kp + 1], bl4[2], bl4[3]);
                    mma16816(S[nf], Ql[2 * kp + 1], bh4[2], bh4[3]);
                }
            }
        }

        // ---- softmax ----
        float mx0 = -1e30f, mx1 = -1e30f;
        float mkx[8], mky[8];
#pragma unroll
        for (int f = 0; f < 8; f++) {
            float2 mk = *(float2*)(smem + (mbx - sbase) + (8 * f + 2 * (lane & 3)) * 4);
            mkx[f] = mk.x; mky[f] = mk.y;
            S[f][0] = (mk.x > 0.f) ? S[f][0] * SCALE : -1e30f;
            S[f][1] = (mk.y > 0.f) ? S[f][1] * SCALE : -1e30f;
            S[f][2] = (mk.x > 0.f) ? S[f][2] * SCALE : -1e30f;
            S[f][3] = (mk.y > 0.f) ? S[f][3] * SCALE : -1e30f;
            mx0 = fmaxf(mx0, fmaxf(S[f][0], S[f][1]));
            mx1 = fmaxf(mx1, fmaxf(S[f][2], S[f][3]));
        }
        mx0 = fmaxf(mx0, __shfl_xor_sync(0xffffffffu, mx0, 1));
        mx0 = fmaxf(mx0, __shfl_xor_sync(0xffffffffu, mx0, 2));
        mx1 = fmaxf(mx1, __shfl_xor_sync(0xffffffffu, mx1, 1));
        mx1 = fmaxf(mx1, __shfl_xor_sync(0xffffffffu, mx1, 2));

        float mn0 = fmaxf(m0r, mx0), mn1 = fmaxf(m1r, mx1);
        float c0 = __expf(m0r - mn0), c1 = __expf(m1r - mn1);

        uint32_t Ph[4][4], Pl[4][4];
        float rs0 = 0.f, rs1 = 0.f;
#pragma unroll
        for (int f = 0; f < 8; f++) {
            float p0 = __expf(S[f][0] - mn0) * mkx[f];
            float p1 = __expf(S[f][1] - mn0) * mky[f];
            float p2 = __expf(S[f][2] - mn1) * mkx[f];
            float p3 = __expf(S[f][3] - mn1) * mky[f];
            rs0 += p0 + p1;
            rs1 += p2 + p3;
            uint32_t h01, l01, h23, l23;
            cvt_split2(p0, p1, h01, l01);
            cvt_split2(p2, p3, h23, l23);
            int kf = f >> 1, half = (f & 1) * 2;
            Ph[kf][half]     = h01;  Ph[kf][half + 1] = h23;
            Pl[kf][half]     = l01;  Pl[kf][half + 1] = l23;
        }
        rs0 += __shfl_xor_sync(0xffffffffu, rs0, 1);
        rs0 += __shfl_xor_sync(0xffffffffu, rs0, 2);
        rs1 += __shfl_xor_sync(0xffffffffu, rs1, 1);
        rs1 += __shfl_xor_sync(0xffffffffu, rs1, 2);

        l0r = l0r * c0 + rs0;  m0r = mn0;
        l1r = l1r * c1 + rs1;  m1r = mn1;
#pragma unroll
        for (int i = 0; i < 8; i++) {
            O[i][0] *= c0; O[i][1] *= c0;
            O[i][2] *= c1; O[i][3] *= c1;
        }

        // ---- O += P V ----
        {
            const uint32_t vaddr0 = vb + ((lane & 7) + 8 * ((lane >> 3) & 1)) * A_STRIDE
                                       + (lane >> 4) * 16;
#pragma unroll
            for (int np = 0; np < 4; np++) {
#pragma unroll
                for (int kf = 0; kf < 4; kf++) {
                    uint32_t bh4[4], bl4[4];
                    uint32_t addr = vaddr0 + kf * (16 * A_STRIDE) + np * 32;
                    ldsm_x4t(bh4, addr);
                    ldsm_x4t(bl4, addr + A_KSZ);
                    mma16816(O[2 * np],     Ph[kf], bh4[0], bh4[1]);
                    mma16816(O[2 * np],     Ph[kf], bl4[0], bl4[1]);
                    mma16816(O[2 * np],     Pl[kf], bh4[0], bh4[1]);
                    mma16816(O[2 * np + 1], Ph[kf], bh4[2], bh4[3]);
                    mma16816(O[2 * np + 1], Ph[kf], bl4[2], bl4[3]);
                    mma16816(O[2 * np + 1], Pl[kf], bh4[2], bh4[3]);
                }
            }
        }

        if (it + 1 < A_NITER) sts_stage((it + 1) & 1);
        __syncthreads();
    }

    // ---- epilogue: normalize, split, write g_ah/g_al ----
    const float inv0 = (l0r > 0.f) ? (1.0f / l0r) : 0.f;
    const float inv1 = (l1r > 0.f) ? (1.0f / l1r) : 0.f;
    const int grow0 = b * T_SEQ + qt * 128 + 16 * w + (lane >> 2);
    const int colb  = h * 64 + 2 * (lane & 3);
#pragma unroll
    for (int nf = 0; nf < 8; nf++) {
        int col = colb + nf * 8;
        uint32_t h01, l01, h23, l23;
        cvt_split2(O[nf][0] * inv0, O[nf][1] * inv0, h01, l01);
        cvt_split2(O[nf][2] * inv1, O[nf][3] * inv1, h23, l23);
        *(uint32_t*)(g_ah + (size_t)grow0 * D_MODEL + col)       = h01;
        *(uint32_t*)(g_al + (size_t)grow0 * D_MODEL + col)       = l01;
        *(uint32_t*)(g_ah + (size_t)(grow0 + 8) * D_MODEL + col) = h23;
        *(uint32_t*)(g_al + (size_t)(grow0 + 8) * D_MODEL + col) = l23;
    }
}

// ---------------------------------------------------------------------------
extern "C" void kernel_launch(void* const* d_in, const int* in_sizes, int n_in,
                              void* d_out, int out_size)
{
    const float* query = (const float*)d_in[0];
    const float* key   = (const float*)d_in[1];
    const float* value = (const float*)d_in[2];
    const int*   mask  = (const int*)d_in[3];
    const float* Wq = (const float*)d_in[4];
    const float* bq = (const float*)d_in[5];
    const float* Wk = (const float*)d_in[6];
    const float* bk = (const float*)d_in[7];
    const float* Wv = (const float*)d_in[8];
    const float* bv = (const float*)d_in[9];
    const float* Wo = (const float*)d_in[10];
    const float* bo = (const float*)d_in[11];
    float* out = (float*)d_out;

    __nv_bfloat16 *xh, *xl, *wh, *wl, *qh, *ql, *kh, *kl, *vh, *vl, *ah, *al;
    cudaGetSymbolAddress((void**)&xh, g_xh);
    cudaGetSymbolAddress((void**)&xl, g_xl);
    cudaGetSymbolAddress((void**)&wh, g_wh);
    cudaGetSymbolAddress((void**)&wl, g_wl);
    cudaGetSymbolAddress((void**)&qh, g_qh);
    cudaGetSymbolAddress((void**)&ql, g_ql);
    cudaGetSymbolAddress((void**)&kh, g_kh);
    cudaGetSymbolAddress((void**)&kl, g_kl);
    cudaGetSymbolAddress((void**)&vh, g_vh);
    cudaGetSymbolAddress((void**)&vl, g_vl);
    cudaGetSymbolAddress((void**)&ah, g_ah);
    cudaGetSymbolAddress((void**)&al, g_al);

    cudaFuncSetAttribute(gemm_mma_kernel, cudaFuncAttributeMaxDynamicSharedMemorySize, G_SMEM_B);
    cudaFuncSetAttribute(attn_mma_kernel, cudaFuncAttributeMaxDynamicSharedMemorySize, A_SMEM);

    const size_t MD = (size_t)M_ROWS * D_MODEL;
    const size_t DD = (size_t)D_MODEL * D_MODEL;
    const int nact4 = (int)(MD / 4);
    const int nw4   = (int)(DD / 4);

    // split inputs (q,k,v) — one launch
    ConvBatch ca;
    ca.src[0] = query; ca.src[1] = key; ca.src[2] = value; ca.src[3] = query;
    ca.hi[0] = xh;        ca.lo[0] = xl;
    ca.hi[1] = xh + MD;   ca.lo[1] = xl + MD;
    ca.hi[2] = xh + 2*MD; ca.lo[2] = xl + 2*MD;
    ca.hi[3] = xh;        ca.lo[3] = xl;
    ca.n4 = nact4;
    conv_split_batched<<<dim3(nact4 / 256, 3), 256>>>(ca);

    // split weights (q,k,v,o) — one launch
    ConvBatch cw;
    cw.src[0] = Wq; cw.src[1] = Wk; cw.src[2] = Wv; cw.src[3] = Wo;
    for (int i = 0; i < 4; i++) { cw.hi[i] = wh + i * DD; cw.lo[i] = wl + i * DD; }
    cw.n4 = nw4;
    conv_split_batched<<<dim3(nw4 / 256, 4), 256>>>(cw);

    // fused Q/K/V projection (split bf16 outputs)
    GemmBatch gb;
    gb.g[0] = { xh,        xl,        wh,        wl,        bq, nullptr, qh, ql };
    gb.g[1] = { xh + MD,   xl + MD,   wh + DD,   wl + DD,   bk, nullptr, kh, kl };
    gb.g[2] = { xh + 2*MD, xl + 2*MD, wh + 2*DD, wl + 2*DD, bv, nullptr, vh, vl };
    gemm_mma_kernel<<<dim3(D_MODEL / 128, M_ROWS / 128, 3), 256, G_SMEM_B>>>(gb, 1);

    // attention (128 q rows per CTA, 256 threads)
    dim3 agrid(T_SEQ / 128, B_BATCH * H_HEADS);   // (16, 32)
    attn_mma_kernel<<<agrid, 256, A_SMEM>>>(mask);

    // output projection (fp32 out)
    GemmBatch go;
    go.g[0] = { ah, al, wh + 3*DD, wl + 3*DD, bo, out, nullptr, nullptr };
    go.g[1] = go.g[0];
    go.g[2] = go.g[0];
    gemm_mma_kernel<<<dim3(D_MODEL / 128, M_ROWS / 128, 1), 256, G_SMEM_B>>>(go, 0);
}